// round 5
// baseline (speedup 1.0000x reference)
#include <cuda_runtime.h>

// MaskedLoss: loss = sum_b sum_{unique (r,c)} (y_true[b,r,c] - y_pred[b,r,c])^2
// B=64, N=1000, K=128. Sparse gather (~8K of 64M positions).
// One fused kernel, 64 blocks (one per batch), last-block-finishes tail with
// scoped atomics (no membar.gl / L1 flush on the critical path).

#define MB_B   64
#define MB_K   128
#define MB_N   1000

// Allocation-free scratch. Zero at module load; the last block restores both
// to 0 every launch, so every graph replay sees identical state.
__device__ float        g_accum;
__device__ unsigned int g_count;

__global__ __launch_bounds__(MB_K)
void masked_loss_fused_kernel(const float* __restrict__ y_true,
                              const float* __restrict__ y_pred,
                              const unsigned int* __restrict__ rows_w,
                              const unsigned int* __restrict__ cols_w,
                              float* __restrict__ out)
{
    const int k = threadIdx.x;   // 0..127 : index-pair id
    const int b = blockIdx.x;    // 0..63  : batch row

    __shared__ int   s_tab[256];     // dedup hash table
    __shared__ float s_red[MB_K / 32];

    // --- init hash table ------------------------------------------------
    s_tab[k]       = -1;
    s_tab[k + 128] = -1;

    // --- speculative L2 prefetch of bytes [512,1024) of each index array.
    // Those bytes hold elements 64..127 in the int64 case (otherwise they are
    // adjacent bytes of the same mapped 2MB page — harmless to prefetch).
    // Overlaps the upper-half miss with the detection load below.
    if (k < 4) {
        const char* p = (const char*)rows_w + 512 + k * 128;
        asm volatile("prefetch.global.L2 [%0];" :: "l"(p));
    } else if (k >= 32 && k < 36) {
        const char* p = (const char*)cols_w + 512 + (k - 32) * 128;
        asm volatile("prefetch.global.L2 [%0];" :: "l"(p));
    }

    // --- index-width detection, barrier-free ------------------------------
    // Each warp samples 32 odd 32-bit words within the first 512B (in-bounds
    // for either width). int64 (values<1000): all hi-words are 0. int32: the
    // 32 samples are random indices in [0,1000) -> all-zero prob ~1e-96.
    // Every warp reaches the same verdict independently; no cross-warp sync.
    const unsigned int probe = rows_w[(((unsigned)k & 63u) << 1) + 1u];
    const bool is_i32 = (__ballot_sync(0xffffffffu, probe != 0u) != 0u);

    int r, c;
    if (is_i32) { r = (int)rows_w[k];         c = (int)cols_w[k];         }
    else        { r = (int)rows_w[2 * k];     c = (int)cols_w[2 * k];     }
    const int my = r * MB_N + c;

    __syncthreads();   // s_tab init visible before CAS

    // --- dedup via shared-mem hash (any single winner per value is fine;
    //     duplicates address the same element) ----------------------------
    unsigned int h = ((unsigned int)my * 2654435761u) >> 24;  // 0..255
    bool uniq = false;
    for (;;) {
        int prev = atomicCAS(&s_tab[h], -1, my);
        if (prev == -1) { uniq = true; break; }
        if (prev == my) break;
        h = (h + 1) & 255;
    }

    // --- gather + squared diff (offset fits in int32: 64e6 + 1e6 < 2^31) --
    float v = 0.0f;
    if (uniq) {
        const int off = b * (MB_N * MB_N) + my;
        const float d = __ldg(y_true + off) - __ldg(y_pred + off);
        v = d * d;
    }

    // --- block reduce (4 warps) -------------------------------------------
    #pragma unroll
    for (int o = 16; o > 0; o >>= 1)
        v += __shfl_down_sync(0xffffffffu, v, o);
    if ((k & 31) == 0) s_red[k >> 5] = v;
    __syncthreads();

    // --- cross-block tail: scoped atomics, no membar.gl --------------------
    if (k == 0) {
        const float bs = s_red[0] + s_red[1] + s_red[2] + s_red[3];

        // relaxed accumulate of the partial
        asm volatile("red.relaxed.gpu.global.add.f32 [%0], %1;"
                     :: "l"(&g_accum), "f"(bs) : "memory");

        // release on the ticket: my accum-add is ordered before my ticket
        unsigned int t;
        asm volatile("atom.release.gpu.global.add.u32 %0, [%1], %2;"
                     : "=r"(t) : "l"(&g_count), "r"(1u) : "memory");

        if (t == MB_B - 1) {   // last block: all 64 accum-adds are at L2
            // acquire + read + reset in one op
            float total; float zero = 0.0f;
            asm volatile("atom.acquire.gpu.global.exch.b32 %0, [%1], %2;"
                         : "=f"(total) : "l"(&g_accum), "f"(zero) : "memory");
            g_count = 0;       // reset for the next graph replay
            out[0] = total;
        }
    }
}

// ---------------------------------------------------------------------------
// Launch contract
//   d_in[0] = y_true  (float32, B*N*N)
//   d_in[1] = y_pred  (float32, B*N*N)
//   d_in[2] = rows    (int64 or int32, K)
//   d_in[3] = cols    (int64 or int32, K)
//   d_out   = float32 scalar
// ---------------------------------------------------------------------------
extern "C" void kernel_launch(void* const* d_in, const int* in_sizes, int n_in,
                              void* d_out, int out_size)
{
    const float*        y_true = (const float*)d_in[0];
    const float*        y_pred = (const float*)d_in[1];
    const unsigned int* rows_w = (const unsigned int*)d_in[2];
    const unsigned int* cols_w = (const unsigned int*)d_in[3];
    float*              out    = (float*)d_out;

    masked_loss_fused_kernel<<<MB_B, MB_K>>>(y_true, y_pred, rows_w, cols_w, out);
}